// round 11
// baseline (speedup 1.0000x reference)
#include <cuda_runtime.h>
#include <cstdint>

// GaussianTrans via mma.sync tf32 (arch-agnostic PTX; tcgen05 is 'a'-gated).
//   outX[b,r,c,d] = sum_h sig(disX+attX) * V[b,r,h,d]   (pass X: write)
//   outY[b,r,c,d] = sum_w sig(disY+attY) * V[b,w,c,d]   (pass Y: accumulate)
// B=16, H=W=64, D=512.
// R9 base (64m x 64n x 64k CTA, 4 warps of 32m x 32n, 5 CTAs/SM) plus
// register double-buffered fragment prefetch in the k-loop: k8+1's LDS issue
// before k8's MMAs, hiding the 29-cyc shared latency under tensor issues.
// X/Y launches interleaved per 4 batches so pass Y's V + outX RMW hit L2.

#define SK 68    // As row stride (pad 4): conflict-free frag loads
#define SN 72    // Vs row stride (pad 8): conflict-free frag loads

static constexpr uint32_t SMEM_BYTES = (64 * SK + 64 * SN) * 4;  // 35840

static __device__ __forceinline__ uint32_t tf32rn(float f) {
    uint32_t r;
    asm("cvt.rn.tf32.f32 %0, %1;" : "=r"(r) : "f"(f));
    return r;
}
static __device__ __forceinline__ float fast_sigmoid(float t) {
    return __fdividef(1.0f, 1.0f + __expf(-t));
}
static __device__ __forceinline__ void mma_tf32(float& c0, float& c1, float& c2,
                                                float& c3, uint32_t a0, uint32_t a1,
                                                uint32_t a2, uint32_t a3,
                                                uint32_t b0, uint32_t b1) {
    asm volatile(
        "mma.sync.aligned.m16n8k8.row.col.f32.tf32.tf32.f32 "
        "{%0,%1,%2,%3}, {%4,%5,%6,%7}, {%8,%9}, {%0,%1,%2,%3};"
        : "+f"(c0), "+f"(c1), "+f"(c2), "+f"(c3)
        : "r"(a0), "r"(a1), "r"(a2), "r"(a3), "r"(b0), "r"(b1));
}

template<bool PASSY>
__global__ __launch_bounds__(128, 5)
void gt_mma(const float* __restrict__ att, const float* __restrict__ V,
            float* __restrict__ out, const float* __restrict__ shift,
            const float* __restrict__ bias, int b0)
{
    extern __shared__ float smem[];
    float* As = smem;             // [64][SK], tf32-RN bit patterns
    float* Vs = smem + 64 * SK;   // [64][SN], raw fp32 (HW truncates to tf32)

    const int tid = threadIdx.x;
    const int dt    = blockIdx.x;          // 0..7 (d tile of 64)
    const int outer = blockIdx.y;          // r (pass X) or c (pass Y)
    const int b     = b0 + blockIdx.z;     // 4 batches per launch

    const float sh = shift[0], bi = bias[0];
    const int attBase = (b * 64 + outer) * 4096;
    const int off     = PASSY ? (b * 2097152 + outer * 512)
                              : ((b * 64 + outer) * 32768);
    const int vstride = PASSY ? 32768 : 512;
    const int dbase   = dt * 64;

    // --- A tile: sigmoid(dis + att) -> tf32-RN; coalesced float4 in ---
    #pragma unroll
    for (int j = 0; j < 8; ++j) {
        const int idx4 = tid + j * 128;          // 1024 float4 = 4096 elems
        const int m  = idx4 >> 4;
        const int k4 = (idx4 & 15) << 2;
        const float4 av = *reinterpret_cast<const float4*>(att + attBase + idx4 * 4);
        float d0 = (float)(k4 + 0 - m);
        float d1 = (float)(k4 + 1 - m);
        float d2 = (float)(k4 + 2 - m);
        float d3 = (float)(k4 + 3 - m);
        uint4 sv;
        sv.x = tf32rn(fast_sigmoid(fmaf(-sh * d0, d0, av.x - bi)));
        sv.y = tf32rn(fast_sigmoid(fmaf(-sh * d1, d1, av.y - bi)));
        sv.z = tf32rn(fast_sigmoid(fmaf(-sh * d2, d2, av.z - bi)));
        sv.w = tf32rn(fast_sigmoid(fmaf(-sh * d3, d3, av.w - bi)));
        *reinterpret_cast<uint4*>(&As[m * SK + k4]) = sv;
    }

    // --- V tile: 64 k-rows x 64 d, raw fp32 bits ---
    #pragma unroll
    for (int j = 0; j < 8; ++j) {
        const int idx4 = tid + j * 128;          // 1024 float4
        const int row  = idx4 >> 4;
        const int col  = (idx4 & 15) << 2;
        const float4 vv = *reinterpret_cast<const float4*>(
            V + off + row * vstride + dbase + col);
        *reinterpret_cast<float4*>(&Vs[row * SN + col]) = vv;
    }
    __syncthreads();

    // --- mma.sync m16n8k8 tf32: warp = 32m x 32n (2 m x 4 n tiles) ---
    const int wid  = tid >> 5;
    const int lane = tid & 31;
    const int grp  = lane >> 2;     // 0..7
    const int tig  = lane & 3;      // 0..3
    const int mrow = (wid & 1) * 32;
    const int n0   = (wid >> 1) * 32;

    float acc[2][4][4];
    #pragma unroll
    for (int mt = 0; mt < 2; ++mt)
        #pragma unroll
        for (int nt = 0; nt < 4; ++nt)
            #pragma unroll
            for (int q = 0; q < 4; ++q) acc[mt][nt][q] = 0.0f;

    const uint32_t* Au = reinterpret_cast<const uint32_t*>(As);
    const uint32_t* Vu = reinterpret_cast<const uint32_t*>(Vs);

    // register double buffers for fragments
    uint32_t a[2][2][4];     // [buf][mt][frag]
    uint32_t bq[2][4][2];    // [buf][nt][frag]

    #define LOAD_FRAGS(BUF, K8) do {                                         \
        const int _kb = (K8) * 8;                                            \
        _Pragma("unroll")                                                    \
        for (int mt = 0; mt < 2; ++mt) {                                     \
            const int base = (mrow + mt * 16 + grp) * SK + _kb + tig;        \
            a[BUF][mt][0] = Au[base];                                        \
            a[BUF][mt][1] = Au[base + 8 * SK];                               \
            a[BUF][mt][2] = Au[base + 4];                                    \
            a[BUF][mt][3] = Au[base + 8 * SK + 4];                           \
        }                                                                    \
        _Pragma("unroll")                                                    \
        for (int nt = 0; nt < 4; ++nt) {                                     \
            const int nc = n0 + nt * 8 + grp;                                \
            bq[BUF][nt][0] = Vu[(_kb + tig) * SN + nc];                      \
            bq[BUF][nt][1] = Vu[(_kb + tig + 4) * SN + nc];                  \
        }                                                                    \
    } while (0)

    LOAD_FRAGS(0, 0);

    #pragma unroll
    for (int k8 = 0; k8 < 8; ++k8) {
        const int cur = k8 & 1;
        const int nxt = cur ^ 1;
        if (k8 < 7) LOAD_FRAGS(nxt, k8 + 1);   // prefetch hides LDS latency
        #pragma unroll
        for (int nt = 0; nt < 4; ++nt)
            #pragma unroll
            for (int mt = 0; mt < 2; ++mt)
                mma_tf32(acc[mt][nt][0], acc[mt][nt][1],
                         acc[mt][nt][2], acc[mt][nt][3],
                         a[cur][mt][0], a[cur][mt][1],
                         a[cur][mt][2], a[cur][mt][3],
                         bq[cur][nt][0], bq[cur][nt][1]);
    }
    #undef LOAD_FRAGS

    // --- epilogue: c0,c1 -> (row, 2 cols); c2,c3 -> (row+8, 2 cols) ---
    #pragma unroll
    for (int mt = 0; mt < 2; ++mt) {
        #pragma unroll
        for (int nt = 0; nt < 4; ++nt) {
            const int col  = dbase + n0 + nt * 8 + tig * 2;
            const int row0 = mrow + mt * 16 + grp;
            float* p0 = out + off + row0 * vstride + col;
            float* p1 = p0 + 8 * vstride;
            float2 w0 = make_float2(acc[mt][nt][0], acc[mt][nt][1]);
            float2 w1 = make_float2(acc[mt][nt][2], acc[mt][nt][3]);
            if (PASSY) {
                const float2 o0 = *reinterpret_cast<const float2*>(p0);
                const float2 o1 = *reinterpret_cast<const float2*>(p1);
                w0.x += o0.x; w0.y += o0.y;
                w1.x += o1.x; w1.y += o1.y;
            }
            *reinterpret_cast<float2*>(p0) = w0;
            *reinterpret_cast<float2*>(p1) = w1;
        }
    }
}

extern "C" void kernel_launch(void* const* d_in, const int* in_sizes, int n_in,
                              void* d_out, int out_size) {
    (void)in_sizes; (void)n_in; (void)out_size;
    // metadata order: x(unused), attentionXFull, attentionYFull, valueFull, shift, bias
    const float* attX  = (const float*)d_in[1];
    const float* attY  = (const float*)d_in[2];
    const float* V     = (const float*)d_in[3];
    const float* shift = (const float*)d_in[4];
    const float* bias  = (const float*)d_in[5];
    float* out = (float*)d_out;

    cudaFuncSetAttribute(gt_mma<false>,
                         cudaFuncAttributeMaxDynamicSharedMemorySize, SMEM_BYTES);
    cudaFuncSetAttribute(gt_mma<true>,
                         cudaFuncAttributeMaxDynamicSharedMemorySize, SMEM_BYTES);

    dim3 grid(8, 64, 4);   // (d-tile of 64, outer, 4 batches) = 2048 CTAs
    dim3 block(128);
    // Interleave per 4 batches: pass Y hits V[b] and outX[b] in L2.
    for (int b0 = 0; b0 < 16; b0 += 4) {
        gt_mma<false><<<grid, block, SMEM_BYTES>>>(attX, V, out, shift, bias, b0);
        gt_mma<true ><<<grid, block, SMEM_BYTES>>>(attY, V, out, shift, bias, b0);
    }
}

// round 12
// speedup vs baseline: 1.0096x; 1.0096x over previous
#include <cuda_runtime.h>
#include <cstdint>

// GaussianTrans via mma.sync tf32 (arch-agnostic PTX; tcgen05 is 'a'-gated).
//   outX[b,r,c,d] = sum_h sig(disX+attX) * V[b,r,h,d]   (pass X: write)
//   outY[b,r,c,d] = sum_w sig(disY+attY) * V[b,w,c,d]   (pass Y: accumulate)
// B=16, H=W=64, D=512.
// R9 base (64m x 64n x 64k CTA, 4 warps of 32m x 32n, 5 CTAs/SM, 2048-CTA
// launches, 4-batch X/Y interleave for L2 reuse) with ONE change:
// sigmoid via tanh.approx (1 MUFU) instead of exp+rcp (2 MUFU), halving the
// MUFU serialization in the fill phase; V LDGs issued first for overlap.

#define SK 68    // As row stride (pad 4): conflict-free frag loads
#define SN 72    // Vs row stride (pad 8): conflict-free frag loads

static constexpr uint32_t SMEM_BYTES = (64 * SK + 64 * SN) * 4;  // 35840

static __device__ __forceinline__ uint32_t tf32rn(float f) {
    uint32_t r;
    asm("cvt.rn.tf32.f32 %0, %1;" : "=r"(r) : "f"(f));
    return r;
}
// sigmoid(t) = 0.5*tanh(t/2) + 0.5  — single MUFU.TANH (sm_75+)
static __device__ __forceinline__ float fast_sigmoid(float t) {
    float th;
    asm("tanh.approx.f32 %0, %1;" : "=f"(th) : "f"(t * 0.5f));
    return fmaf(th, 0.5f, 0.5f);
}
static __device__ __forceinline__ void mma_tf32(float& c0, float& c1, float& c2,
                                                float& c3, uint32_t a0, uint32_t a1,
                                                uint32_t a2, uint32_t a3,
                                                uint32_t b0, uint32_t b1) {
    asm volatile(
        "mma.sync.aligned.m16n8k8.row.col.f32.tf32.tf32.f32 "
        "{%0,%1,%2,%3}, {%4,%5,%6,%7}, {%8,%9}, {%0,%1,%2,%3};"
        : "+f"(c0), "+f"(c1), "+f"(c2), "+f"(c3)
        : "r"(a0), "r"(a1), "r"(a2), "r"(a3), "r"(b0), "r"(b1));
}

template<bool PASSY>
__global__ __launch_bounds__(128, 5)
void gt_mma(const float* __restrict__ att, const float* __restrict__ V,
            float* __restrict__ out, const float* __restrict__ shift,
            const float* __restrict__ bias, int b0)
{
    extern __shared__ float smem[];
    float* As = smem;             // [64][SK], tf32-RN bit patterns
    float* Vs = smem + 64 * SK;   // [64][SN], raw fp32 (HW truncates to tf32)

    const int tid = threadIdx.x;
    const int dt    = blockIdx.x;          // 0..7 (d tile of 64)
    const int outer = blockIdx.y;          // r (pass X) or c (pass Y)
    const int b     = b0 + blockIdx.z;     // 4 batches per launch

    const float sh = shift[0], bi = bias[0];
    const int attBase = (b * 64 + outer) * 4096;
    const int off     = PASSY ? (b * 2097152 + outer * 512)
                              : ((b * 64 + outer) * 32768);
    const int vstride = PASSY ? 32768 : 512;
    const int dbase   = dt * 64;

    // --- V tile first: 64 k-rows x 64 d, raw fp32 bits (DRAM latency overlaps
    //     the A-fill math below) ---
    #pragma unroll
    for (int j = 0; j < 8; ++j) {
        const int idx4 = tid + j * 128;          // 1024 float4
        const int row  = idx4 >> 4;
        const int col  = (idx4 & 15) << 2;
        const float4 vv = *reinterpret_cast<const float4*>(
            V + off + row * vstride + dbase + col);
        *reinterpret_cast<float4*>(&Vs[row * SN + col]) = vv;
    }

    // --- A tile: sigmoid(dis + att) -> tf32-RN; coalesced float4 in ---
    #pragma unroll
    for (int j = 0; j < 8; ++j) {
        const int idx4 = tid + j * 128;          // 1024 float4 = 4096 elems
        const int m  = idx4 >> 4;
        const int k4 = (idx4 & 15) << 2;
        const float4 av = *reinterpret_cast<const float4*>(att + attBase + idx4 * 4);
        float d0 = (float)(k4 + 0 - m);
        float d1 = (float)(k4 + 1 - m);
        float d2 = (float)(k4 + 2 - m);
        float d3 = (float)(k4 + 3 - m);
        uint4 sv;
        sv.x = tf32rn(fast_sigmoid(fmaf(-sh * d0, d0, av.x - bi)));
        sv.y = tf32rn(fast_sigmoid(fmaf(-sh * d1, d1, av.y - bi)));
        sv.z = tf32rn(fast_sigmoid(fmaf(-sh * d2, d2, av.z - bi)));
        sv.w = tf32rn(fast_sigmoid(fmaf(-sh * d3, d3, av.w - bi)));
        *reinterpret_cast<uint4*>(&As[m * SK + k4]) = sv;
    }
    __syncthreads();

    // --- mma.sync m16n8k8 tf32: warp = 32m x 32n (2 m-tiles x 4 n-tiles) ---
    const int wid  = tid >> 5;
    const int lane = tid & 31;
    const int grp  = lane >> 2;     // 0..7
    const int tig  = lane & 3;      // 0..3
    const int mrow = (wid & 1) * 32;
    const int n0   = (wid >> 1) * 32;

    float acc[2][4][4];
    #pragma unroll
    for (int mt = 0; mt < 2; ++mt)
        #pragma unroll
        for (int nt = 0; nt < 4; ++nt)
            #pragma unroll
            for (int q = 0; q < 4; ++q) acc[mt][nt][q] = 0.0f;

    const uint32_t* Au = reinterpret_cast<const uint32_t*>(As);
    const uint32_t* Vu = reinterpret_cast<const uint32_t*>(Vs);

    #pragma unroll
    for (int k8 = 0; k8 < 8; ++k8) {
        const int kb = k8 * 8;
        uint32_t a[2][4];
        #pragma unroll
        for (int mt = 0; mt < 2; ++mt) {
            const int base = (mrow + mt * 16 + grp) * SK + kb + tig;
            a[mt][0] = Au[base];                 // (row,   col)
            a[mt][1] = Au[base + 8 * SK];        // (row+8, col)
            a[mt][2] = Au[base + 4];             // (row,   col+4)
            a[mt][3] = Au[base + 8 * SK + 4];    // (row+8, col+4)
        }
        #pragma unroll
        for (int nt = 0; nt < 4; ++nt) {
            const int nc = n0 + nt * 8 + grp;
            const uint32_t bq0 = Vu[(kb + tig) * SN + nc];
            const uint32_t bq1 = Vu[(kb + tig + 4) * SN + nc];
            #pragma unroll
            for (int mt = 0; mt < 2; ++mt)
                mma_tf32(acc[mt][nt][0], acc[mt][nt][1],
                         acc[mt][nt][2], acc[mt][nt][3],
                         a[mt][0], a[mt][1], a[mt][2], a[mt][3], bq0, bq1);
        }
    }

    // --- epilogue: c0,c1 -> (row, 2 cols); c2,c3 -> (row+8, 2 cols) ---
    #pragma unroll
    for (int mt = 0; mt < 2; ++mt) {
        #pragma unroll
        for (int nt = 0; nt < 4; ++nt) {
            const int col  = dbase + n0 + nt * 8 + tig * 2;
            const int row0 = mrow + mt * 16 + grp;
            float* p0 = out + off + row0 * vstride + col;
            float* p1 = p0 + 8 * vstride;
            float2 w0 = make_float2(acc[mt][nt][0], acc[mt][nt][1]);
            float2 w1 = make_float2(acc[mt][nt][2], acc[mt][nt][3]);
            if (PASSY) {
                const float2 o0 = *reinterpret_cast<const float2*>(p0);
                const float2 o1 = *reinterpret_cast<const float2*>(p1);
                w0.x += o0.x; w0.y += o0.y;
                w1.x += o1.x; w1.y += o1.y;
            }
            *reinterpret_cast<float2*>(p0) = w0;
            *reinterpret_cast<float2*>(p1) = w1;
        }
    }
}

extern "C" void kernel_launch(void* const* d_in, const int* in_sizes, int n_in,
                              void* d_out, int out_size) {
    (void)in_sizes; (void)n_in; (void)out_size;
    // metadata order: x(unused), attentionXFull, attentionYFull, valueFull, shift, bias
    const float* attX  = (const float*)d_in[1];
    const float* attY  = (const float*)d_in[2];
    const float* V     = (const float*)d_in[3];
    const float* shift = (const float*)d_in[4];
    const float* bias  = (const float*)d_in[5];
    float* out = (float*)d_out;

    cudaFuncSetAttribute(gt_mma<false>,
                         cudaFuncAttributeMaxDynamicSharedMemorySize, SMEM_BYTES);
    cudaFuncSetAttribute(gt_mma<true>,
                         cudaFuncAttributeMaxDynamicSharedMemorySize, SMEM_BYTES);

    dim3 grid(8, 64, 4);   // (d-tile of 64, outer, 4 batches) = 2048 CTAs
    dim3 block(128);
    // Interleave per 4 batches: pass Y hits V[b] and outX[b] in L2.
    for (int b0 = 0; b0 < 16; b0 += 4) {
        gt_mma<false><<<grid, block, SMEM_BYTES>>>(attX, V, out, shift, bias, b0);
        gt_mma<true ><<<grid, block, SMEM_BYTES>>>(attY, V, out, shift, bias, b0);
    }
}